// round 15
// baseline (speedup 1.0000x reference)
#include <cuda_runtime.h>
#include <cuda_fp16.h>
#include <math.h>
#include <stdint.h>

#define BB 8
#define CC 256
#define HFD 160
#define WFD 160
#define NN 128
#define SS 7
#define HP 161
#define NBOX (BB*NN)                       // 1024
#define NREG (SS*SS)                       // 49
#define NTOT (NBOX*NREG)                   // 50176
#define RF_ELEMS ((size_t)NBOX*CC*NREG)    // 12,845,056
#define SLAB 8
#define CSTR 164
#define NSTRIP 20
#define SROWS 8

// -------- scratch --------
__device__ float  g_I[(size_t)BB*HP*HP*CC];               // strip-LOCAL integrals [b][hp][wp][c]
__device__ float  g_P[(size_t)BB*NSTRIP*HP*CC];           // strip prefix offsets [b][s][wp][c]
__device__ __align__(16) __half g_regh[(size_t)NTOT*CC];  // region avgs fp16 [n][c]
__device__ __align__(16) __half g_Wh[CC*CC];              // W fp16 [o][c]

__device__ __forceinline__ uint32_t smem_u32(const void* p) {
    uint32_t a;
    asm("{ .reg .u64 t; cvta.to.shared.u64 t, %1; cvt.u32.u64 %0, t; }"
        : "=r"(a) : "l"(p));
    return a;
}

// ============================================================
// K0: W -> fp16
// ============================================================
__global__ void k_convw(const float* __restrict__ Wm) {
    int i = blockIdx.x * 256 + threadIdx.x;
    g_Wh[i] = __float2half_rn(Wm[i]);
}

// ============================================================
// K1a: strip-local 2D integral, ONE batch (param b).
// CTA = (8-ch slab, strip). Warp = one channel.
// ============================================================
__global__ void __launch_bounds__(256) k_integral(const float* __restrict__ fm, int b) {
    __shared__ float stg[2][SLAB*CSTR];
    const int s  = blockIdx.y;
    const int c0 = blockIdx.x * SLAB;
    const int tid = threadIdx.x, w = tid >> 5, lane = tid & 31;
    const int c = c0 + w;

    const float* in  = fm + ((size_t)(b*CC + c)*HFD + s*SROWS)*WFD;
    float* outb = g_I + (((size_t)b*HP)*HP)*CC + c0;

    if (s == 0) {
        for (int idx = tid; idx < HP*SLAB; idx += 256) {
            int wp = idx >> 3, cc = idx & 7;
            outb[(size_t)wp*CC + cc] = 0.f;
        }
    }

    float colsum[5] = {0.f, 0.f, 0.f, 0.f, 0.f};
    float v[5];
    #pragma unroll
    for (int j = 0; j < 5; ++j) v[j] = in[j*32 + lane];

    #pragma unroll
    for (int r = 0; r < SROWS; ++r) {
        float nv[5] = {0.f, 0.f, 0.f, 0.f, 0.f};
        if (r + 1 < SROWS) {
            #pragma unroll
            for (int j = 0; j < 5; ++j) nv[j] = in[(size_t)(r+1)*WFD + j*32 + lane];
        }

        #pragma unroll
        for (int off = 1; off < 32; off <<= 1) {
            #pragma unroll
            for (int j = 0; j < 5; ++j) {
                float n = __shfl_up_sync(0xffffffffu, v[j], off);
                if (lane >= off) v[j] += n;
            }
        }
        float pre = 0.f;
        #pragma unroll
        for (int j = 0; j < 5; ++j) {
            float tot = __shfl_sync(0xffffffffu, v[j], 31);
            v[j] += pre;
            pre += tot;
        }

        const int p = r & 1;
        #pragma unroll
        for (int j = 0; j < 5; ++j) {
            colsum[j] += v[j];
            stg[p][w*CSTR + j*32 + lane] = colsum[j];
        }
        __syncthreads();

        float* orow = outb + (size_t)(s*SROWS + r + 1)*HP*CC;
        for (int idx = tid; idx < HP*4; idx += 256) {
            int wp = idx >> 2, cp = idx & 3;
            float2 val;
            if (wp == 0) { val.x = 0.f; val.y = 0.f; }
            else {
                val.x = stg[p][(cp*2    )*CSTR + (wp-1)];
                val.y = stg[p][(cp*2 + 1)*CSTR + (wp-1)];
            }
            *(float2*)(orow + (size_t)wp*CC + cp*2) = val;
        }

        #pragma unroll
        for (int j = 0; j < 5; ++j) v[j] = nv[j];
    }
}

// ============================================================
// K1b: strip prefix P, ONE batch (param b).
// ============================================================
__global__ void __launch_bounds__(256) k_strippfx(int b) {
    const int wp = blockIdx.x;
    const int c  = threadIdx.x;

    const float* I = g_I + (((size_t)b*HP)*HP + wp)*CC + c;
    float* P = g_P + (((size_t)b*NSTRIP)*HP + wp)*CC + c;
    P[0] = 0.f;
    float acc = 0.f;
    #pragma unroll
    for (int s = 1; s < NSTRIP; ++s) {
        acc += I[(size_t)(s*SROWS)*HP*CC];
        P[(size_t)s*HP*CC] = acc;
    }
}

// ============================================================
// K3: corner gather, ONE batch (param b). CTA = (box-in-batch, i-row).
// ============================================================
__global__ void __launch_bounds__(64) k_gather(const float* __restrict__ bboxes,
                                               float* __restrict__ out_area, int b) {
    const int box = b*NN + blockIdx.x;
    const int i   = blockIdx.y;
    const int t   = threadIdx.x;

    const float bx1 = bboxes[box*4+0];
    const float by1 = bboxes[box*4+1];
    const float bx2 = bboxes[box*4+2];
    const float by2 = bboxes[box*4+3];
    if (i == 0 && t == 0) out_area[box] = (bx2-bx1)*(by2-by1);

    int x1 = (int)floorf(bx1*0.25f); x1 = min(max(x1, 0), WFD-1);
    int y1 = (int)floorf(by1*0.25f); y1 = min(max(y1, 0), HFD-1);
    int x2 = (int)floorf(bx2*0.25f); x2 = min(max(x2, x1+1), WFD);
    int y2 = (int)floorf(by2*0.25f); y2 = min(max(y2, y1+1), HFD);
    const int Lx = x2 - x1, Ly = y2 - y1;

    const int hpS = y1 + (i*Ly)/SS;
    const int hpE = y1 + ((i+1)*Ly + SS-1)/SS;

    int cs[SS], ce[SS];
    #pragma unroll
    for (int j = 0; j < SS; ++j) {
        cs[j] = x1 + (j*Lx)/SS;
        ce[j] = x1 + ((j+1)*Lx + SS-1)/SS;
    }

    const float4* I4 = (const float4*)g_I + (size_t)b*HP*HP*64 + t;
    const float4* P4 = (const float4*)g_P + (size_t)b*NSTRIP*HP*64 + t;

    const int sS = (hpS > 0) ? ((hpS-1) >> 3) : 0;
    const int sE = (hpE-1) >> 3;
    const float4* rowS = I4 + (size_t)hpS*HP*64;
    const float4* rowE = I4 + (size_t)hpE*HP*64;
    const float4* PS = P4 + (size_t)sS*HP*64;
    const float4* PE = P4 + (size_t)sE*HP*64;
    const float inv_dh = 1.f / (float)(hpE - hpS);

    __half2* outp = (__half2*)(g_regh + (size_t)box*(NREG*CC) + i*SS*CC) + 2*t;

    #pragma unroll
    for (int j = 0; j < SS; ++j) {
        const int wS = cs[j]*64, wE = ce[j]*64;
        float4 tl = rowS[wS], tr = rowS[wE];
        float4 bl = rowE[wS], br = rowE[wE];
        float4 ptl = PS[wS], ptr_ = PS[wE];
        float4 pbl = PE[wS], pbr = PE[wE];
        float inv = inv_dh / (float)(ce[j]-cs[j]);
        float vx = ((br.x + pbr.x) - (tr.x + ptr_.x) - (bl.x + pbl.x) + (tl.x + ptl.x)) * inv;
        float vy = ((br.y + pbr.y) - (tr.y + ptr_.y) - (bl.y + pbl.y) + (tl.y + ptl.y)) * inv;
        float vz = ((br.z + pbr.z) - (tr.z + ptr_.z) - (bl.z + pbl.z) + (tl.z + ptl.z)) * inv;
        float vw = ((br.w + pbr.w) - (tr.w + ptr_.w) - (bl.w + pbl.w) + (tl.w + ptl.w)) * inv;
        __half2 h0 = __floats2half2_rn(vx, vy);
        __half2 h1 = __floats2half2_rn(vz, vw);
        uint2 pk;
        pk.x = *(uint32_t*)&h0;
        pk.y = *(uint32_t*)&h1;
        *(uint2*)(outp + (size_t)j*128) = pk;
    }
}

// ============================================================
// K4: mma.sync f16 GEMM (proven 128x128 config, B via ldmatrix.x4).
// ============================================================
#define AB_BUF 16384
#define B_OFF  32768
#define GEMM_SMEM 66048
#define STG_LD 129

__global__ void __launch_bounds__(256, 2) k_mma_gemm(const float* __restrict__ bias,
                                                     float* __restrict__ out) {
    extern __shared__ char sm[];
    const uint32_t sb = smem_u32(sm);
    const int tid = threadIdx.x, wid = tid >> 5, lane = tid & 31;
    const int m0 = blockIdx.x * 128;
    const int n0 = blockIdx.y * 128;

    auto issue = [&](int kc, int p) {
        #pragma unroll
        for (int it = 0; it < 4; ++it) {
            int u = tid + it*256;
            int row = u >> 3, kb = u & 7;
            uint32_t off = (uint32_t)(row*128 + ((kb ^ (row & 7)) << 4));
            const __half* asrc = g_Wh   + (size_t)(m0 + row)*CC + kc*64 + kb*8;
            const __half* bsrc = g_regh + (size_t)(n0 + row)*CC + kc*64 + kb*8;
            uint32_t da = sb + p*AB_BUF + off;
            uint32_t db = sb + B_OFF + p*AB_BUF + off;
            asm volatile("cp.async.cg.shared.global [%0], [%1], 16;" :: "r"(da), "l"(asrc));
            asm volatile("cp.async.cg.shared.global [%0], [%1], 16;" :: "r"(db), "l"(bsrc));
        }
        asm volatile("cp.async.commit_group;");
    };

    const int wm = wid >> 2;
    const int wn = wid & 3;
    const int a_l15 = lane & 15;
    const int a_khi = lane >> 4;

    uint32_t a_row[4], a_xr[4];
    #pragma unroll
    for (int mf = 0; mf < 4; ++mf) {
        int mrow = wm*64 + mf*16 + a_l15;
        a_row[mf] = (uint32_t)(mrow*128);
        a_xr[mf] = (uint32_t)(mrow & 7);
    }

    const int bq   = lane >> 3;
    const int b_l7 = lane & 7;
    const int b_k4 = bq & 1;
    uint32_t b4_row[2], b4_xr[2];
    #pragma unroll
    for (int g = 0; g < 2; ++g) {
        int nrow = wn*32 + (g*2 + (bq >> 1))*8 + b_l7;
        b4_row[g] = (uint32_t)(nrow*128);
        b4_xr[g] = (uint32_t)(nrow & 7);
    }

    float acc[4][4][4];
    #pragma unroll
    for (int mf = 0; mf < 4; ++mf)
        #pragma unroll
        for (int nf = 0; nf < 4; ++nf)
            #pragma unroll
            for (int e = 0; e < 4; ++e) acc[mf][nf][e] = 0.f;

    issue(0, 0);

    #pragma unroll
    for (int kc = 0; kc < 4; ++kc) {
        const int p = kc & 1;
        if (kc < 3) {
            issue(kc+1, (kc+1) & 1);
            asm volatile("cp.async.wait_group 1;" ::: "memory");
        } else {
            asm volatile("cp.async.wait_group 0;" ::: "memory");
        }
        __syncthreads();

        #pragma unroll
        for (int ks = 0; ks < 4; ++ks) {
            uint32_t a[4][4], b[4][2];
            #pragma unroll
            for (int mf = 0; mf < 4; ++mf) {
                uint32_t kb = (uint32_t)(ks*2 + a_khi) ^ a_xr[mf];
                uint32_t addr = sb + p*AB_BUF + a_row[mf] + (kb << 4);
                asm volatile("ldmatrix.sync.aligned.m8n8.x4.shared.b16 {%0,%1,%2,%3}, [%4];"
                             : "=r"(a[mf][0]), "=r"(a[mf][1]), "=r"(a[mf][2]), "=r"(a[mf][3])
                             : "r"(addr));
            }
            #pragma unroll
            for (int g = 0; g < 2; ++g) {
                uint32_t kb = (uint32_t)(ks*2 + b_k4) ^ b4_xr[g];
                uint32_t addr = sb + B_OFF + p*AB_BUF + b4_row[g] + (kb << 4);
                asm volatile("ldmatrix.sync.aligned.m8n8.x4.shared.b16 {%0,%1,%2,%3}, [%4];"
                             : "=r"(b[g*2][0]), "=r"(b[g*2][1]),
                               "=r"(b[g*2+1][0]), "=r"(b[g*2+1][1])
                             : "r"(addr));
            }
            #pragma unroll
            for (int mf = 0; mf < 4; ++mf)
                #pragma unroll
                for (int nf = 0; nf < 4; ++nf) {
                    asm volatile(
                        "mma.sync.aligned.m16n8k16.row.col.f32.f16.f16.f32 "
                        "{%0,%1,%2,%3}, {%4,%5,%6,%7}, {%8,%9}, {%0,%1,%2,%3};"
                        : "+f"(acc[mf][nf][0]), "+f"(acc[mf][nf][1]),
                          "+f"(acc[mf][nf][2]), "+f"(acc[mf][nf][3])
                        : "r"(a[mf][0]), "r"(a[mf][1]), "r"(a[mf][2]), "r"(a[mf][3]),
                          "r"(b[nf][0]), "r"(b[nf][1]));
                }
        }
        __syncthreads();
    }

    float* stgf = (float*)sm;
    const int crow = lane >> 2;
    const int ccol = (lane & 3) * 2;
    #pragma unroll
    for (int mf = 0; mf < 4; ++mf) {
        int mr = wm*64 + mf*16 + crow;
        #pragma unroll
        for (int nf = 0; nf < 4; ++nf) {
            int nc = wn*32 + nf*8 + ccol;
            stgf[mr*STG_LD + nc]         = acc[mf][nf][0];
            stgf[mr*STG_LD + nc + 1]     = acc[mf][nf][1];
            stgf[(mr+8)*STG_LD + nc]     = acc[mf][nf][2];
            stgf[(mr+8)*STG_LD + nc + 1] = acc[mf][nf][3];
        }
    }
    __syncthreads();

    #pragma unroll 4
    for (int i = tid; i < 128*128; i += 256) {
        int m = i >> 7, n = i & 127;
        int nn = n0 + n, o = m0 + m;
        int box = nn / NREG, r = nn - box*NREG;
        out[(size_t)box*(CC*NREG) + (size_t)o*NREG + r] = stgf[m*STG_LD + n] + bias[o];
    }
}

// ============================================================
// Launch: two forked streams (capture-legal event fork/join).
// sI: per-batch integrals.  sR: convw, then per-batch pfx+gather.
// origin: joins sR, runs full GEMM.
// ============================================================
extern "C" void kernel_launch(void* const* d_in, const int* in_sizes, int n_in,
                              void* d_out, int out_size) {
    const float* fm     = (const float*)d_in[0];
    const float* bboxes = (const float*)d_in[1];
    const float* Wm     = (const float*)d_in[2];
    const float* bias   = (const float*)d_in[3];
    float* out = (float*)d_out;

    static cudaStream_t sI = nullptr, sR = nullptr;
    static cudaEvent_t evStart = nullptr, evI[BB], evR = nullptr;
    if (sI == nullptr) {                    // first (uncaptured) call only
        cudaStreamCreateWithFlags(&sI, cudaStreamNonBlocking);
        cudaStreamCreateWithFlags(&sR, cudaStreamNonBlocking);
        cudaEventCreateWithFlags(&evStart, cudaEventDisableTiming);
        for (int b = 0; b < BB; ++b)
            cudaEventCreateWithFlags(&evI[b], cudaEventDisableTiming);
        cudaEventCreateWithFlags(&evR, cudaEventDisableTiming);
        cudaFuncSetAttribute(k_mma_gemm, cudaFuncAttributeMaxDynamicSharedMemorySize,
                             GEMM_SMEM);
    }

    // fork
    cudaEventRecord(evStart, 0);
    cudaStreamWaitEvent(sI, evStart, 0);
    cudaStreamWaitEvent(sR, evStart, 0);

    k_convw<<<CC, 256, 0, sR>>>(Wm);

    dim3 g1(CC/SLAB, NSTRIP);               // 32 x 20 per batch
    dim3 g3(NN, SS);                        // 128 x 7 per batch
    for (int b = 0; b < BB; ++b) {
        k_integral<<<g1, 256, 0, sI>>>(fm, b);
        cudaEventRecord(evI[b], sI);
        cudaStreamWaitEvent(sR, evI[b], 0);
        k_strippfx<<<HP, 256, 0, sR>>>(b);
        k_gather<<<g3, 64, 0, sR>>>(bboxes, out + RF_ELEMS, b);
    }

    // join
    cudaEventRecord(evR, sR);
    cudaStreamWaitEvent(0, evR, 0);

    dim3 g4(2, NTOT/128);                   // 2 x 392
    k_mma_gemm<<<g4, 256, GEMM_SMEM>>>(bias, out);
}

// round 16
// speedup vs baseline: 1.3494x; 1.3494x over previous
#include <cuda_runtime.h>
#include <cuda_fp16.h>
#include <math.h>
#include <stdint.h>

#define BB 8
#define CC 256
#define HFD 160
#define WFD 160
#define NN 128
#define SS 7
#define HP 161
#define NBOX (BB*NN)                       // 1024
#define NREG (SS*SS)                       // 49
#define NTOT (NBOX*NREG)                   // 50176
#define RF_ELEMS ((size_t)NBOX*CC*NREG)    // 12,845,056
#define SLAB 8
#define CSTR 164
#define NSTRIP 20
#define SROWS 8
#define BGRP 4                             // batches per group

// -------- scratch --------
__device__ float  g_I[(size_t)BB*HP*HP*CC];               // strip-LOCAL integrals [b][hp][wp][c]
__device__ float  g_P[(size_t)BB*NSTRIP*HP*CC];           // strip prefix offsets [b][s][wp][c]
__device__ __align__(16) __half g_regh[(size_t)NTOT*CC];  // region avgs fp16 [n][c]
__device__ __align__(16) __half g_Wh[CC*CC];              // W fp16 [o][c]

__device__ __forceinline__ uint32_t smem_u32(const void* p) {
    uint32_t a;
    asm("{ .reg .u64 t; cvta.to.shared.u64 t, %1; cvt.u32.u64 %0, t; }"
        : "=r"(a) : "l"(p));
    return a;
}

// ============================================================
// K0: W -> fp16
// ============================================================
__global__ void k_convw(const float* __restrict__ Wm) {
    int i = blockIdx.x * 256 + threadIdx.x;
    g_Wh[i] = __float2half_rn(Wm[i]);
}

// ============================================================
// K1a: strip-local 2D integral (R11 body), batch group of 4.
// grid (32, 20, 4): b = b0 + blockIdx.z.
// ============================================================
__global__ void __launch_bounds__(256) k_integral(const float* __restrict__ fm, int b0) {
    __shared__ float stg[2][SLAB*CSTR];
    const int b  = b0 + blockIdx.z;
    const int s  = blockIdx.y;
    const int c0 = blockIdx.x * SLAB;
    const int tid = threadIdx.x, w = tid >> 5, lane = tid & 31;
    const int c = c0 + w;

    const float* in  = fm + ((size_t)(b*CC + c)*HFD + s*SROWS)*WFD;
    float* outb = g_I + (((size_t)b*HP)*HP)*CC + c0;

    if (s == 0) {
        for (int idx = tid; idx < HP*SLAB; idx += 256) {
            int wp = idx >> 3, cc = idx & 7;
            outb[(size_t)wp*CC + cc] = 0.f;
        }
    }

    float colsum[5] = {0.f, 0.f, 0.f, 0.f, 0.f};
    float v[5];
    #pragma unroll
    for (int j = 0; j < 5; ++j) v[j] = in[j*32 + lane];

    #pragma unroll
    for (int r = 0; r < SROWS; ++r) {
        float nv[5] = {0.f, 0.f, 0.f, 0.f, 0.f};
        if (r + 1 < SROWS) {
            #pragma unroll
            for (int j = 0; j < 5; ++j) nv[j] = in[(size_t)(r+1)*WFD + j*32 + lane];
        }

        #pragma unroll
        for (int off = 1; off < 32; off <<= 1) {
            #pragma unroll
            for (int j = 0; j < 5; ++j) {
                float n = __shfl_up_sync(0xffffffffu, v[j], off);
                if (lane >= off) v[j] += n;
            }
        }
        float pre = 0.f;
        #pragma unroll
        for (int j = 0; j < 5; ++j) {
            float tot = __shfl_sync(0xffffffffu, v[j], 31);
            v[j] += pre;
            pre += tot;
        }

        const int p = r & 1;
        #pragma unroll
        for (int j = 0; j < 5; ++j) {
            colsum[j] += v[j];
            stg[p][w*CSTR + j*32 + lane] = colsum[j];
        }
        __syncthreads();

        float* orow = outb + (size_t)(s*SROWS + r + 1)*HP*CC;
        for (int idx = tid; idx < HP*4; idx += 256) {
            int wp = idx >> 2, cp = idx & 3;
            float2 val;
            if (wp == 0) { val.x = 0.f; val.y = 0.f; }
            else {
                val.x = stg[p][(cp*2    )*CSTR + (wp-1)];
                val.y = stg[p][(cp*2 + 1)*CSTR + (wp-1)];
            }
            *(float2*)(orow + (size_t)wp*CC + cp*2) = val;
        }

        #pragma unroll
        for (int j = 0; j < 5; ++j) v[j] = nv[j];
    }
}

// ============================================================
// K1b: strip prefix P, batch group of 4. grid (161, 4).
// ============================================================
__global__ void __launch_bounds__(256) k_strippfx(int b0) {
    const int b  = b0 + blockIdx.y;
    const int wp = blockIdx.x;
    const int c  = threadIdx.x;

    const float* I = g_I + (((size_t)b*HP)*HP + wp)*CC + c;
    float* P = g_P + (((size_t)b*NSTRIP)*HP + wp)*CC + c;
    P[0] = 0.f;
    float acc = 0.f;
    #pragma unroll
    for (int s = 1; s < NSTRIP; ++s) {
        acc += I[(size_t)(s*SROWS)*HP*CC];
        P[(size_t)s*HP*CC] = acc;
    }
}

// ============================================================
// K3: corner gather (R11 body), batch group of 4. grid (512, 7).
// ============================================================
__global__ void __launch_bounds__(64) k_gather(const float* __restrict__ bboxes,
                                               float* __restrict__ out_area, int b0) {
    const int box = b0*NN + blockIdx.x;
    const int i   = blockIdx.y;
    const int b   = box >> 7;
    const int t   = threadIdx.x;

    const float bx1 = bboxes[box*4+0];
    const float by1 = bboxes[box*4+1];
    const float bx2 = bboxes[box*4+2];
    const float by2 = bboxes[box*4+3];
    if (i == 0 && t == 0) out_area[box] = (bx2-bx1)*(by2-by1);

    int x1 = (int)floorf(bx1*0.25f); x1 = min(max(x1, 0), WFD-1);
    int y1 = (int)floorf(by1*0.25f); y1 = min(max(y1, 0), HFD-1);
    int x2 = (int)floorf(bx2*0.25f); x2 = min(max(x2, x1+1), WFD);
    int y2 = (int)floorf(by2*0.25f); y2 = min(max(y2, y1+1), HFD);
    const int Lx = x2 - x1, Ly = y2 - y1;

    const int hpS = y1 + (i*Ly)/SS;
    const int hpE = y1 + ((i+1)*Ly + SS-1)/SS;

    int cs[SS], ce[SS];
    #pragma unroll
    for (int j = 0; j < SS; ++j) {
        cs[j] = x1 + (j*Lx)/SS;
        ce[j] = x1 + ((j+1)*Lx + SS-1)/SS;
    }

    const float4* I4 = (const float4*)g_I + (size_t)b*HP*HP*64 + t;
    const float4* P4 = (const float4*)g_P + (size_t)b*NSTRIP*HP*64 + t;

    const int sS = (hpS > 0) ? ((hpS-1) >> 3) : 0;
    const int sE = (hpE-1) >> 3;
    const float4* rowS = I4 + (size_t)hpS*HP*64;
    const float4* rowE = I4 + (size_t)hpE*HP*64;
    const float4* PS = P4 + (size_t)sS*HP*64;
    const float4* PE = P4 + (size_t)sE*HP*64;
    const float inv_dh = 1.f / (float)(hpE - hpS);

    __half2* outp = (__half2*)(g_regh + (size_t)box*(NREG*CC) + i*SS*CC) + 2*t;

    #pragma unroll
    for (int j = 0; j < SS; ++j) {
        const int wS = cs[j]*64, wE = ce[j]*64;
        float4 tl = rowS[wS], tr = rowS[wE];
        float4 bl = rowE[wS], br = rowE[wE];
        float4 ptl = PS[wS], ptr_ = PS[wE];
        float4 pbl = PE[wS], pbr = PE[wE];
        float inv = inv_dh / (float)(ce[j]-cs[j]);
        float vx = ((br.x + pbr.x) - (tr.x + ptr_.x) - (bl.x + pbl.x) + (tl.x + ptl.x)) * inv;
        float vy = ((br.y + pbr.y) - (tr.y + ptr_.y) - (bl.y + pbl.y) + (tl.y + ptl.y)) * inv;
        float vz = ((br.z + pbr.z) - (tr.z + ptr_.z) - (bl.z + pbl.z) + (tl.z + ptl.z)) * inv;
        float vw = ((br.w + pbr.w) - (tr.w + ptr_.w) - (bl.w + pbl.w) + (tl.w + ptl.w)) * inv;
        __half2 h0 = __floats2half2_rn(vx, vy);
        __half2 h1 = __floats2half2_rn(vz, vw);
        uint2 pk;
        pk.x = *(uint32_t*)&h0;
        pk.y = *(uint32_t*)&h1;
        *(uint2*)(outp + (size_t)j*128) = pk;
    }
}

// ============================================================
// K4: mma.sync f16 GEMM (R11 proven config).
// ============================================================
#define AB_BUF 16384
#define B_OFF  32768
#define GEMM_SMEM 66048
#define STG_LD 129

__global__ void __launch_bounds__(256, 2) k_mma_gemm(const float* __restrict__ bias,
                                                     float* __restrict__ out) {
    extern __shared__ char sm[];
    const uint32_t sb = smem_u32(sm);
    const int tid = threadIdx.x, wid = tid >> 5, lane = tid & 31;
    const int m0 = blockIdx.x * 128;
    const int n0 = blockIdx.y * 128;

    auto issue = [&](int kc, int p) {
        #pragma unroll
        for (int it = 0; it < 4; ++it) {
            int u = tid + it*256;
            int row = u >> 3, kb = u & 7;
            uint32_t off = (uint32_t)(row*128 + ((kb ^ (row & 7)) << 4));
            const __half* asrc = g_Wh   + (size_t)(m0 + row)*CC + kc*64 + kb*8;
            const __half* bsrc = g_regh + (size_t)(n0 + row)*CC + kc*64 + kb*8;
            uint32_t da = sb + p*AB_BUF + off;
            uint32_t db = sb + B_OFF + p*AB_BUF + off;
            asm volatile("cp.async.cg.shared.global [%0], [%1], 16;" :: "r"(da), "l"(asrc));
            asm volatile("cp.async.cg.shared.global [%0], [%1], 16;" :: "r"(db), "l"(bsrc));
        }
        asm volatile("cp.async.commit_group;");
    };

    const int wm = wid >> 2;
    const int wn = wid & 3;
    const int a_l15 = lane & 15;
    const int a_khi = lane >> 4;
    const int b_l7  = lane & 7;
    const int b_khi = (lane >> 3) & 1;

    uint32_t a_row[4], a_xr[4], b_row[4], b_xr[4];
    #pragma unroll
    for (int mf = 0; mf < 4; ++mf) {
        int mrow = wm*64 + mf*16 + a_l15;
        a_row[mf] = (uint32_t)(mrow*128);
        a_xr[mf] = (uint32_t)(mrow & 7);
    }
    #pragma unroll
    for (int nf = 0; nf < 4; ++nf) {
        int nrow = wn*32 + nf*8 + b_l7;
        b_row[nf] = (uint32_t)(nrow*128);
        b_xr[nf] = (uint32_t)(nrow & 7);
    }

    float acc[4][4][4];
    #pragma unroll
    for (int mf = 0; mf < 4; ++mf)
        #pragma unroll
        for (int nf = 0; nf < 4; ++nf)
            #pragma unroll
            for (int e = 0; e < 4; ++e) acc[mf][nf][e] = 0.f;

    issue(0, 0);

    #pragma unroll
    for (int kc = 0; kc < 4; ++kc) {
        const int p = kc & 1;
        if (kc < 3) {
            issue(kc+1, (kc+1) & 1);
            asm volatile("cp.async.wait_group 1;" ::: "memory");
        } else {
            asm volatile("cp.async.wait_group 0;" ::: "memory");
        }
        __syncthreads();

        #pragma unroll
        for (int ks = 0; ks < 4; ++ks) {
            uint32_t a[4][4], b[4][2];
            #pragma unroll
            for (int mf = 0; mf < 4; ++mf) {
                uint32_t kb = (uint32_t)(ks*2 + a_khi) ^ a_xr[mf];
                uint32_t addr = sb + p*AB_BUF + a_row[mf] + (kb << 4);
                asm volatile("ldmatrix.sync.aligned.m8n8.x4.shared.b16 {%0,%1,%2,%3}, [%4];"
                             : "=r"(a[mf][0]), "=r"(a[mf][1]), "=r"(a[mf][2]), "=r"(a[mf][3])
                             : "r"(addr));
            }
            #pragma unroll
            for (int nf = 0; nf < 4; ++nf) {
                uint32_t kb = (uint32_t)(ks*2 + b_khi) ^ b_xr[nf];
                uint32_t addr = sb + B_OFF + p*AB_BUF + b_row[nf] + (kb << 4);
                asm volatile("ldmatrix.sync.aligned.m8n8.x2.shared.b16 {%0,%1}, [%2];"
                             : "=r"(b[nf][0]), "=r"(b[nf][1])
                             : "r"(addr));
            }
            #pragma unroll
            for (int mf = 0; mf < 4; ++mf)
                #pragma unroll
                for (int nf = 0; nf < 4; ++nf) {
                    asm volatile(
                        "mma.sync.aligned.m16n8k16.row.col.f32.f16.f16.f32 "
                        "{%0,%1,%2,%3}, {%4,%5,%6,%7}, {%8,%9}, {%0,%1,%2,%3};"
                        : "+f"(acc[mf][nf][0]), "+f"(acc[mf][nf][1]),
                          "+f"(acc[mf][nf][2]), "+f"(acc[mf][nf][3])
                        : "r"(a[mf][0]), "r"(a[mf][1]), "r"(a[mf][2]), "r"(a[mf][3]),
                          "r"(b[nf][0]), "r"(b[nf][1]));
                }
        }
        __syncthreads();
    }

    float* stgf = (float*)sm;
    const int crow = lane >> 2;
    const int ccol = (lane & 3) * 2;
    #pragma unroll
    for (int mf = 0; mf < 4; ++mf) {
        int mr = wm*64 + mf*16 + crow;
        #pragma unroll
        for (int nf = 0; nf < 4; ++nf) {
            int nc = wn*32 + nf*8 + ccol;
            stgf[mr*STG_LD + nc]         = acc[mf][nf][0];
            stgf[mr*STG_LD + nc + 1]     = acc[mf][nf][1];
            stgf[(mr+8)*STG_LD + nc]     = acc[mf][nf][2];
            stgf[(mr+8)*STG_LD + nc + 1] = acc[mf][nf][3];
        }
    }
    __syncthreads();

    #pragma unroll 4
    for (int i = tid; i < 128*128; i += 256) {
        int m = i >> 7, n = i & 127;
        int nn = n0 + n, o = m0 + m;
        int box = nn / NREG, r = nn - box*NREG;
        out[(size_t)box*(CC*NREG) + (size_t)o*NREG + r] = stgf[m*STG_LD + n] + bias[o];
    }
}

// ============================================================
// Launch: coarse 2-group overlap (4 cross-stream edges total).
// ============================================================
extern "C" void kernel_launch(void* const* d_in, const int* in_sizes, int n_in,
                              void* d_out, int out_size) {
    const float* fm     = (const float*)d_in[0];
    const float* bboxes = (const float*)d_in[1];
    const float* Wm     = (const float*)d_in[2];
    const float* bias   = (const float*)d_in[3];
    float* out = (float*)d_out;

    static cudaStream_t sI = nullptr, sR = nullptr;
    static cudaEvent_t evStart = nullptr, evA = nullptr, evB = nullptr, evR = nullptr;
    if (sI == nullptr) {                    // first (uncaptured) call only
        cudaStreamCreateWithFlags(&sI, cudaStreamNonBlocking);
        cudaStreamCreateWithFlags(&sR, cudaStreamNonBlocking);
        cudaEventCreateWithFlags(&evStart, cudaEventDisableTiming);
        cudaEventCreateWithFlags(&evA, cudaEventDisableTiming);
        cudaEventCreateWithFlags(&evB, cudaEventDisableTiming);
        cudaEventCreateWithFlags(&evR, cudaEventDisableTiming);
        cudaFuncSetAttribute(k_mma_gemm, cudaFuncAttributeMaxDynamicSharedMemorySize,
                             GEMM_SMEM);
    }

    // fork
    cudaEventRecord(evStart, 0);
    cudaStreamWaitEvent(sI, evStart, 0);
    cudaStreamWaitEvent(sR, evStart, 0);

    k_convw<<<CC, 256, 0, sR>>>(Wm);

    dim3 g1(CC/SLAB, NSTRIP, BGRP);        // 32 x 20 x 4 per group
    dim3 gp(HP, BGRP);                     // 161 x 4 per group
    dim3 g3(NN*BGRP, SS);                  // 512 x 7 per group

    k_integral<<<g1, 256, 0, sI>>>(fm, 0);
    cudaEventRecord(evA, sI);
    k_integral<<<g1, 256, 0, sI>>>(fm, BGRP);
    cudaEventRecord(evB, sI);

    cudaStreamWaitEvent(sR, evA, 0);
    k_strippfx<<<gp, 256, 0, sR>>>(0);
    k_gather<<<g3, 64, 0, sR>>>(bboxes, out + RF_ELEMS, 0);
    cudaStreamWaitEvent(sR, evB, 0);
    k_strippfx<<<gp, 256, 0, sR>>>(BGRP);
    k_gather<<<g3, 64, 0, sR>>>(bboxes, out + RF_ELEMS, BGRP);

    // join
    cudaEventRecord(evR, sR);
    cudaStreamWaitEvent(0, evR, 0);

    dim3 g4(2, NTOT/128);                  // 2 x 392
    k_mma_gemm<<<g4, 256, GEMM_SMEM>>>(bias, out);
}

// round 17
// speedup vs baseline: 1.5629x; 1.1582x over previous
#include <cuda_runtime.h>
#include <cuda_fp16.h>
#include <math.h>
#include <stdint.h>

#define BB 8
#define CC 256
#define HFD 160
#define WFD 160
#define NN 128
#define SS 7
#define HP 161
#define NBOX (BB*NN)                       // 1024
#define NREG (SS*SS)                       // 49
#define NTOT (NBOX*NREG)                   // 50176
#define RF_ELEMS ((size_t)NBOX*CC*NREG)    // 12,845,056
#define SLAB 8
#define CSTR 164
#define NSTRIP 20
#define SROWS 8

// -------- scratch --------
__device__ float  g_I[(size_t)BB*HP*HP*CC];               // strip-LOCAL integrals [b][hp][wp][c]
__device__ float  g_P[(size_t)BB*NSTRIP*HP*CC];           // strip prefix offsets [b][s][wp][c]
__device__ __align__(16) __half g_regh[(size_t)NTOT*CC];  // region avgs fp16 [n][c]
__device__ __align__(16) __half g_Wh[CC*CC];              // W fp16 [o][c]

__device__ __forceinline__ uint32_t smem_u32(const void* p) {
    uint32_t a;
    asm("{ .reg .u64 t; cvta.to.shared.u64 t, %1; cvt.u32.u64 %0, t; }"
        : "=r"(a) : "l"(p));
    return a;
}

// ============================================================
// K1a: strip-local 2D integral. CTA = (8-ch slab, strip, batch).
// Warp = one channel. Lane-serial scan: each lane owns 5 consecutive
// elements (via per-warp smem transpose), 4 serial adds + ONE 5-level
// warp scan of lane totals. ~45 instr/row/warp vs 75 before.
// ============================================================
__global__ void __launch_bounds__(256) k_integral(const float* __restrict__ fm) {
    __shared__ float raw[2][SLAB][WFD];          // 10.0 KB
    __shared__ float stg[2][SLAB*CSTR];          // 10.5 KB
    const int b  = blockIdx.z;
    const int s  = blockIdx.y;
    const int c0 = blockIdx.x * SLAB;
    const int tid = threadIdx.x, w = tid >> 5, lane = tid & 31;
    const int c = c0 + w;

    const float* in  = fm + ((size_t)(b*CC + c)*HFD + s*SROWS)*WFD;
    float* outb = g_I + (((size_t)b*HP)*HP)*CC + c0;

    if (s == 0) {
        for (int idx = tid; idx < HP*SLAB; idx += 256) {
            int wp = idx >> 3, cc = idx & 7;
            outb[(size_t)wp*CC + cc] = 0.f;
        }
    }

    // prologue: stage row 0 into raw[0] (coalesced)
    #pragma unroll
    for (int j = 0; j < 5; ++j)
        raw[0][w][j*32 + lane] = in[j*32 + lane];

    float colsum[5] = {0.f, 0.f, 0.f, 0.f, 0.f};   // layout: w-pos = lane*5 + k

    #pragma unroll
    for (int r = 0; r < SROWS; ++r) {
        const int p2 = r & 1;

        // prefetch next row into registers (overlaps with scan)
        float nv[5] = {0.f, 0.f, 0.f, 0.f, 0.f};
        if (r + 1 < SROWS) {
            #pragma unroll
            for (int j = 0; j < 5; ++j) nv[j] = in[(size_t)(r+1)*WFD + j*32 + lane];
        }

        __syncwarp();                              // raw[p2] STS -> LDS visibility
        float t[5];
        #pragma unroll
        for (int k = 0; k < 5; ++k) t[k] = raw[p2][w][lane*5 + k];

        // lane-serial inclusive scan of 5 elements
        t[1] += t[0]; t[2] += t[1]; t[3] += t[2]; t[4] += t[3];
        const float own = t[4];

        // warp inclusive scan of lane totals
        float tot = own;
        #pragma unroll
        for (int off = 1; off < 32; off <<= 1) {
            float n = __shfl_up_sync(0xffffffffu, tot, off);
            if (lane >= off) tot += n;
        }
        const float excl = tot - own;

        const int p = r & 1;
        #pragma unroll
        for (int k = 0; k < 5; ++k) {
            colsum[k] += t[k] + excl;
            stg[p][w*CSTR + lane*5 + k] = colsum[k];   // stride-5: conflict-free
        }
        __syncthreads();

        // cooperative coalesced store of integral row hp = s*SROWS + r + 1
        float* orow = outb + (size_t)(s*SROWS + r + 1)*HP*CC;
        for (int idx = tid; idx < HP*4; idx += 256) {
            int wp = idx >> 2, cp = idx & 3;
            float2 val;
            if (wp == 0) { val.x = 0.f; val.y = 0.f; }
            else {
                val.x = stg[p][(cp*2    )*CSTR + (wp-1)];
                val.y = stg[p][(cp*2 + 1)*CSTR + (wp-1)];
            }
            *(float2*)(orow + (size_t)wp*CC + cp*2) = val;
        }

        // stage prefetched row for next iteration
        if (r + 1 < SROWS) {
            #pragma unroll
            for (int j = 0; j < 5; ++j)
                raw[(r+1) & 1][w][j*32 + lane] = nv[j];
        }
    }
}

// ============================================================
// K1b: strip prefix P + (first 256 CTAs) W->fp16 conversion.
// ============================================================
__global__ void __launch_bounds__(256) k_strippfx(const float* __restrict__ Wm) {
    const int b  = blockIdx.y;
    const int wp = blockIdx.x;
    const int c  = threadIdx.x;

    const int flat = blockIdx.x + HP*blockIdx.y;
    if (flat < CC)
        g_Wh[flat*CC + c] = __float2half_rn(Wm[flat*CC + c]);

    const float* I = g_I + (((size_t)b*HP)*HP + wp)*CC + c;
    float* P = g_P + (((size_t)b*NSTRIP)*HP + wp)*CC + c;
    P[0] = 0.f;
    float acc = 0.f;
    #pragma unroll
    for (int s = 1; s < NSTRIP; ++s) {
        acc += I[(size_t)(s*SROWS)*HP*CC];
        P[(size_t)s*HP*CC] = acc;
    }
}

// ============================================================
// K3: corner gather, float4 loads / 8-B half stores.
// CTA = (box, i-row); 64 threads (thread = channel quad).
// ============================================================
__global__ void __launch_bounds__(64) k_gather(const float* __restrict__ bboxes,
                                               float* __restrict__ out_area) {
    const int box = blockIdx.x;
    const int i   = blockIdx.y;
    const int b   = box >> 7;
    const int t   = threadIdx.x;

    const float bx1 = bboxes[box*4+0];
    const float by1 = bboxes[box*4+1];
    const float bx2 = bboxes[box*4+2];
    const float by2 = bboxes[box*4+3];
    if (i == 0 && t == 0) out_area[box] = (bx2-bx1)*(by2-by1);

    int x1 = (int)floorf(bx1*0.25f); x1 = min(max(x1, 0), WFD-1);
    int y1 = (int)floorf(by1*0.25f); y1 = min(max(y1, 0), HFD-1);
    int x2 = (int)floorf(bx2*0.25f); x2 = min(max(x2, x1+1), WFD);
    int y2 = (int)floorf(by2*0.25f); y2 = min(max(y2, y1+1), HFD);
    const int Lx = x2 - x1, Ly = y2 - y1;

    const int hpS = y1 + (i*Ly)/SS;
    const int hpE = y1 + ((i+1)*Ly + SS-1)/SS;

    int cs[SS], ce[SS];
    #pragma unroll
    for (int j = 0; j < SS; ++j) {
        cs[j] = x1 + (j*Lx)/SS;
        ce[j] = x1 + ((j+1)*Lx + SS-1)/SS;
    }

    const float4* I4 = (const float4*)g_I + (size_t)b*HP*HP*64 + t;
    const float4* P4 = (const float4*)g_P + (size_t)b*NSTRIP*HP*64 + t;

    const int sS = (hpS > 0) ? ((hpS-1) >> 3) : 0;
    const int sE = (hpE-1) >> 3;
    const float4* rowS = I4 + (size_t)hpS*HP*64;
    const float4* rowE = I4 + (size_t)hpE*HP*64;
    const float4* PS = P4 + (size_t)sS*HP*64;
    const float4* PE = P4 + (size_t)sE*HP*64;
    const float inv_dh = 1.f / (float)(hpE - hpS);

    __half2* outp = (__half2*)(g_regh + (size_t)box*(NREG*CC) + i*SS*CC) + 2*t;

    #pragma unroll
    for (int j = 0; j < SS; ++j) {
        const int wS = cs[j]*64, wE = ce[j]*64;
        float4 tl = rowS[wS], tr = rowS[wE];
        float4 bl = rowE[wS], br = rowE[wE];
        float4 ptl = PS[wS], ptr_ = PS[wE];
        float4 pbl = PE[wS], pbr = PE[wE];
        float inv = inv_dh / (float)(ce[j]-cs[j]);
        float vx = ((br.x + pbr.x) - (tr.x + ptr_.x) - (bl.x + pbl.x) + (tl.x + ptl.x)) * inv;
        float vy = ((br.y + pbr.y) - (tr.y + ptr_.y) - (bl.y + pbl.y) + (tl.y + ptl.y)) * inv;
        float vz = ((br.z + pbr.z) - (tr.z + ptr_.z) - (bl.z + pbl.z) + (tl.z + ptl.z)) * inv;
        float vw = ((br.w + pbr.w) - (tr.w + ptr_.w) - (bl.w + pbl.w) + (tl.w + ptl.w)) * inv;
        __half2 h0 = __floats2half2_rn(vx, vy);
        __half2 h1 = __floats2half2_rn(vz, vw);
        uint2 pk;
        pk.x = *(uint32_t*)&h0;
        pk.y = *(uint32_t*)&h1;
        *(uint2*)(outp + (size_t)j*128) = pk;
    }
}

// ============================================================
// K4: mma.sync f16 GEMM (R11 proven config).
// CTA tile 128x128, K chunked (4 x 64), 2-stage cp.async,
// __launch_bounds__(256, 2) -> regs <= 128 -> 2 CTAs/SM.
// ============================================================
#define AB_BUF 16384
#define B_OFF  32768
#define GEMM_SMEM 66048
#define STG_LD 129

__global__ void __launch_bounds__(256, 2) k_mma_gemm(const float* __restrict__ bias,
                                                     float* __restrict__ out) {
    extern __shared__ char sm[];
    const uint32_t sb = smem_u32(sm);
    const int tid = threadIdx.x, wid = tid >> 5, lane = tid & 31;
    const int m0 = blockIdx.x * 128;
    const int n0 = blockIdx.y * 128;

    auto issue = [&](int kc, int p) {
        #pragma unroll
        for (int it = 0; it < 4; ++it) {
            int u = tid + it*256;
            int row = u >> 3, kb = u & 7;
            uint32_t off = (uint32_t)(row*128 + ((kb ^ (row & 7)) << 4));
            const __half* asrc = g_Wh   + (size_t)(m0 + row)*CC + kc*64 + kb*8;
            const __half* bsrc = g_regh + (size_t)(n0 + row)*CC + kc*64 + kb*8;
            uint32_t da = sb + p*AB_BUF + off;
            uint32_t db = sb + B_OFF + p*AB_BUF + off;
            asm volatile("cp.async.cg.shared.global [%0], [%1], 16;" :: "r"(da), "l"(asrc));
            asm volatile("cp.async.cg.shared.global [%0], [%1], 16;" :: "r"(db), "l"(bsrc));
        }
        asm volatile("cp.async.commit_group;");
    };

    const int wm = wid >> 2;
    const int wn = wid & 3;
    const int a_l15 = lane & 15;
    const int a_khi = lane >> 4;
    const int b_l7  = lane & 7;
    const int b_khi = (lane >> 3) & 1;

    uint32_t a_row[4], a_xr[4], b_row[4], b_xr[4];
    #pragma unroll
    for (int mf = 0; mf < 4; ++mf) {
        int mrow = wm*64 + mf*16 + a_l15;
        a_row[mf] = (uint32_t)(mrow*128);
        a_xr[mf] = (uint32_t)(mrow & 7);
    }
    #pragma unroll
    for (int nf = 0; nf < 4; ++nf) {
        int nrow = wn*32 + nf*8 + b_l7;
        b_row[nf] = (uint32_t)(nrow*128);
        b_xr[nf] = (uint32_t)(nrow & 7);
    }

    float acc[4][4][4];
    #pragma unroll
    for (int mf = 0; mf < 4; ++mf)
        #pragma unroll
        for (int nf = 0; nf < 4; ++nf)
            #pragma unroll
            for (int e = 0; e < 4; ++e) acc[mf][nf][e] = 0.f;

    issue(0, 0);

    #pragma unroll
    for (int kc = 0; kc < 4; ++kc) {
        const int p = kc & 1;
        if (kc < 3) {
            issue(kc+1, (kc+1) & 1);
            asm volatile("cp.async.wait_group 1;" ::: "memory");
        } else {
            asm volatile("cp.async.wait_group 0;" ::: "memory");
        }
        __syncthreads();

        #pragma unroll
        for (int ks = 0; ks < 4; ++ks) {
            uint32_t a[4][4], b[4][2];
            #pragma unroll
            for (int mf = 0; mf < 4; ++mf) {
                uint32_t kb = (uint32_t)(ks*2 + a_khi) ^ a_xr[mf];
                uint32_t addr = sb + p*AB_BUF + a_row[mf] + (kb << 4);
                asm volatile("ldmatrix.sync.aligned.m8n8.x4.shared.b16 {%0,%1,%2,%3}, [%4];"
                             : "=r"(a[mf][0]), "=r"(a[mf][1]), "=r"(a[mf][2]), "=r"(a[mf][3])
                             : "r"(addr));
            }
            #pragma unroll
            for (int nf = 0; nf < 4; ++nf) {
                uint32_t kb = (uint32_t)(ks*2 + b_khi) ^ b_xr[nf];
                uint32_t addr = sb + B_OFF + p*AB_BUF + b_row[nf] + (kb << 4);
                asm volatile("ldmatrix.sync.aligned.m8n8.x2.shared.b16 {%0,%1}, [%2];"
                             : "=r"(b[nf][0]), "=r"(b[nf][1])
                             : "r"(addr));
            }
            #pragma unroll
            for (int mf = 0; mf < 4; ++mf)
                #pragma unroll
                for (int nf = 0; nf < 4; ++nf) {
                    asm volatile(
                        "mma.sync.aligned.m16n8k16.row.col.f32.f16.f16.f32 "
                        "{%0,%1,%2,%3}, {%4,%5,%6,%7}, {%8,%9}, {%0,%1,%2,%3};"
                        : "+f"(acc[mf][nf][0]), "+f"(acc[mf][nf][1]),
                          "+f"(acc[mf][nf][2]), "+f"(acc[mf][nf][3])
                        : "r"(a[mf][0]), "r"(a[mf][1]), "r"(a[mf][2]), "r"(a[mf][3]),
                          "r"(b[nf][0]), "r"(b[nf][1]));
                }
        }
        __syncthreads();
    }

    float* stgf = (float*)sm;
    const int crow = lane >> 2;
    const int ccol = (lane & 3) * 2;
    #pragma unroll
    for (int mf = 0; mf < 4; ++mf) {
        int mr = wm*64 + mf*16 + crow;
        #pragma unroll
        for (int nf = 0; nf < 4; ++nf) {
            int nc = wn*32 + nf*8 + ccol;
            stgf[mr*STG_LD + nc]         = acc[mf][nf][0];
            stgf[mr*STG_LD + nc + 1]     = acc[mf][nf][1];
            stgf[(mr+8)*STG_LD + nc]     = acc[mf][nf][2];
            stgf[(mr+8)*STG_LD + nc + 1] = acc[mf][nf][3];
        }
    }
    __syncthreads();

    #pragma unroll 4
    for (int i = tid; i < 128*128; i += 256) {
        int m = i >> 7, n = i & 127;
        int nn = n0 + n, o = m0 + m;
        int box = nn / NREG, r = nn - box*NREG;
        out[(size_t)box*(CC*NREG) + (size_t)o*NREG + r] = stgf[m*STG_LD + n] + bias[o];
    }
}

// ============================================================
extern "C" void kernel_launch(void* const* d_in, const int* in_sizes, int n_in,
                              void* d_out, int out_size) {
    const float* fm     = (const float*)d_in[0];
    const float* bboxes = (const float*)d_in[1];
    const float* Wm     = (const float*)d_in[2];
    const float* bias   = (const float*)d_in[3];
    float* out = (float*)d_out;

    cudaFuncSetAttribute(k_mma_gemm, cudaFuncAttributeMaxDynamicSharedMemorySize,
                         GEMM_SMEM);

    dim3 g1(CC/SLAB, NSTRIP, BB);          // 32 x 20 x 8 = 5120 CTAs
    k_integral<<<g1, 256>>>(fm);

    dim3 gp(HP, BB);
    k_strippfx<<<gp, 256>>>(Wm);

    dim3 g3(NBOX, SS);                     // 1024 x 7
    k_gather<<<g3, 64>>>(bboxes, out + RF_ELEMS);

    dim3 g4(2, NTOT/128);                  // 2 x 392
    k_mma_gemm<<<g4, 256, GEMM_SMEM>>>(bias, out);
}